// round 1
// baseline (speedup 1.0000x reference)
#include <cuda_runtime.h>
#include <math.h>

#define NN 50000
#define EE 800000
#define NIN 256
#define NH 128
#define NOUT 64
#define NHOP 10

// ---------------- scratch (static device memory; no allocations) -------------
__device__ float g_x [(size_t)NN * NH];   // fc1 output (constant across hops)
__device__ float g_h [(size_t)NN * NH];   // current h
__device__ float g_xn[(size_t)NN * NH];   // x @ W_i + b
__device__ float g_hn[(size_t)NN * NH];   // h @ W_i + b
__device__ float g_x1[NN];
__device__ float g_h1[NN];
__device__ float g_w2[NN];
__device__ int   g_deg[NN];
__device__ int   g_rowptr[NN + 1];
__device__ int   g_cursor[NN];
__device__ int   g_et[EE];

// ---------------- CSR build --------------------------------------------------
__global__ void hist_kernel(const int* __restrict__ s) {
    int e = blockIdx.x * blockDim.x + threadIdx.x;
    if (e < EE) atomicAdd(&g_deg[s[e]], 1);
}

__global__ void scan_kernel() {
    __shared__ int sh[1024];
    __shared__ int carry_s;
    int tid = threadIdx.x;
    if (tid == 0) { carry_s = 0; g_rowptr[0] = 0; }
    __syncthreads();
    for (int base = 0; base < NN; base += 1024) {
        int v = (base + tid < NN) ? g_deg[base + tid] : 0;
        sh[tid] = v;
        __syncthreads();
        for (int off = 1; off < 1024; off <<= 1) {
            int add = (tid >= off) ? sh[tid - off] : 0;
            __syncthreads();
            sh[tid] += add;
            __syncthreads();
        }
        int incl = sh[tid];
        int c = carry_s;
        if (base + tid < NN) {
            g_rowptr[base + tid + 1] = c + incl;
            g_cursor[base + tid]     = c + incl - v;
        }
        __syncthreads();
        if (tid == 0) carry_s = c + sh[1023];
        __syncthreads();
    }
}

__global__ void scatter_kernel(const int* __restrict__ s, const int* __restrict__ t) {
    int e = blockIdx.x * blockDim.x + threadIdx.x;
    if (e < EE) {
        int pos = atomicAdd(&g_cursor[s[e]], 1);
        g_et[pos] = t[e];
    }
}

// ---------------- tiled GEMM: C = act(A @ W^T + b) ---------------------------
// A: [nrows, K] row-major, W: [NCOLS, K] row-major, C: [nrows, NCOLS].
// Block tile: 128 rows x NCOLS cols, 256 threads, 8 x (NCOLS/16) per thread.
// blockIdx.y selects (A0,C0) vs (A1,C1) so x-path and h-path run in one launch.
template <int NCOLS, int ACT>
__global__ __launch_bounds__(256)
void gemm_kernel(const float* __restrict__ A0, const float* __restrict__ A1,
                 const float* __restrict__ W,  const float* __restrict__ bias,
                 float* __restrict__ C0, float* __restrict__ C1,
                 int nrows, int K) {
    constexpr int KC = 32;
    constexpr int BM = 128;
    constexpr int LD = KC + 1;       // 33: bank-conflict-free strided access
    constexpr int TN = NCOLS / 16;

    const float* A = blockIdx.y ? A1 : A0;
    float*       C = blockIdx.y ? C1 : C0;

    extern __shared__ float smem[];
    float* As = smem;                 // [BM][LD]
    float* Ws = smem + BM * LD;       // [NCOLS][LD]

    int tid = threadIdx.x;
    int tm = tid >> 4;                // 0..15  (rows tm + 16*i)
    int tj = tid & 15;                // 0..15  (cols tj + 16*j)
    int rbase = blockIdx.x * BM;

    float acc[8][TN];
#pragma unroll
    for (int i = 0; i < 8; i++)
#pragma unroll
        for (int j = 0; j < TN; j++) acc[i][j] = 0.f;

    for (int kc = 0; kc < K; kc += KC) {
        __syncthreads();
        // load A tile: 128 x 32 floats = 1024 float4, 4 per thread
#pragma unroll
        for (int it = 0; it < 4; it++) {
            int idx = tid + it * 256;
            int r = idx >> 3, kq = idx & 7;
            int row = rbase + r;
            float4 v = make_float4(0.f, 0.f, 0.f, 0.f);
            if (row < nrows) v = *(const float4*)(A + (size_t)row * K + kc + kq * 4);
            float* d = &As[r * LD + kq * 4];
            d[0] = v.x; d[1] = v.y; d[2] = v.z; d[3] = v.w;
        }
        // load W tile: NCOLS x 32 floats
#pragma unroll
        for (int it = 0; it < NCOLS / 32; it++) {
            int idx = tid + it * 256;
            int r = idx >> 3, kq = idx & 7;
            float4 v = *(const float4*)(W + (size_t)r * K + kc + kq * 4);
            float* d = &Ws[r * LD + kq * 4];
            d[0] = v.x; d[1] = v.y; d[2] = v.z; d[3] = v.w;
        }
        __syncthreads();
#pragma unroll 8
        for (int k = 0; k < KC; k++) {
            float a[8], w[TN];
#pragma unroll
            for (int i = 0; i < 8; i++) a[i] = As[(tm + 16 * i) * LD + k];
#pragma unroll
            for (int j = 0; j < TN; j++) w[j] = Ws[(tj + 16 * j) * LD + k];
#pragma unroll
            for (int i = 0; i < 8; i++)
#pragma unroll
                for (int j = 0; j < TN; j++)
                    acc[i][j] = fmaf(a[i], w[j], acc[i][j]);
        }
    }

    float bv[TN];
#pragma unroll
    for (int j = 0; j < TN; j++) bv[j] = bias[tj + 16 * j];
#pragma unroll
    for (int i = 0; i < 8; i++) {
        int row = rbase + tm + 16 * i;
        if (row < nrows) {
#pragma unroll
            for (int j = 0; j < TN; j++) {
                float v = acc[i][j] + bv[j];
                if (ACT) v = fmaxf(v, 0.f);
                C[(size_t)row * NCOLS + tj + 16 * j] = v;
            }
        }
    }
}

// ---------------- per-node attention vectors ---------------------------------
// x1[n] = xn[n]·a1 ; w2[n] = exp(lrelu(x1 + xn[n]·a2)) ; h1[n] = hn[n]·a2
__global__ void vec_kernel(const float* __restrict__ xn, const float* __restrict__ hn,
                           const float* __restrict__ a1, const float* __restrict__ a2) {
    int n = (blockIdx.x * blockDim.x + threadIdx.x) >> 5;
    int lane = threadIdx.x & 31;
    if (n >= NN) return;
    float4 a1v = *(const float4*)(a1 + lane * 4);
    float4 a2v = *(const float4*)(a2 + lane * 4);
    float4 xv  = *(const float4*)(xn + (size_t)n * NH + lane * 4);
    float4 hv  = *(const float4*)(hn + (size_t)n * NH + lane * 4);
    float s1 = xv.x * a1v.x + xv.y * a1v.y + xv.z * a1v.z + xv.w * a1v.w;
    float s2 = xv.x * a2v.x + xv.y * a2v.y + xv.z * a2v.z + xv.w * a2v.w;
    float s3 = hv.x * a2v.x + hv.y * a2v.y + hv.z * a2v.z + hv.w * a2v.w;
#pragma unroll
    for (int off = 16; off; off >>= 1) {
        s1 += __shfl_down_sync(0xffffffffu, s1, off);
        s2 += __shfl_down_sync(0xffffffffu, s2, off);
        s3 += __shfl_down_sync(0xffffffffu, s3, off);
    }
    if (lane == 0) {
        g_x1[n] = s1;
        float z = s1 + s2;
        z = z > 0.f ? z : 0.2f * z;
        g_w2[n] = __expf(z);
        g_h1[n] = s3;
    }
}

// ---------------- CSR aggregation (one warp per destination node) ------------
// h_out[n] = elu( (sum_e w1_e * hn[t_e] + w2[n]*xn[n]) / (sum_e w1_e + w2[n]) )
__global__ void agg_kernel(const float* __restrict__ xn, const float* __restrict__ hn,
                           float* __restrict__ hout) {
    int n = (blockIdx.x * blockDim.x + threadIdx.x) >> 5;
    int lane = threadIdx.x & 31;
    if (n >= NN) return;

    float x1n = g_x1[n];
    float w2n = g_w2[n];
    float4 acc = *(const float4*)(xn + (size_t)n * NH + lane * 4);
    acc.x *= w2n; acc.y *= w2n; acc.z *= w2n; acc.w *= w2n;
    float div = w2n;

    int e  = g_rowptr[n];
    int e1 = g_rowptr[n + 1];
    for (; e < e1; e++) {
        int t = g_et[e];
        float z = x1n + g_h1[t];
        z = z > 0.f ? z : 0.2f * z;
        float w = __expf(z);
        div += w;
        float4 hv = *(const float4*)(hn + (size_t)t * NH + lane * 4);
        acc.x = fmaf(w, hv.x, acc.x);
        acc.y = fmaf(w, hv.y, acc.y);
        acc.z = fmaf(w, hv.z, acc.z);
        acc.w = fmaf(w, hv.w, acc.w);
    }
    float inv = 1.0f / div;
    float4 o;
    o.x = acc.x * inv; o.y = acc.y * inv; o.z = acc.z * inv; o.w = acc.w * inv;
    o.x = o.x > 0.f ? o.x : expm1f(o.x);
    o.y = o.y > 0.f ? o.y : expm1f(o.y);
    o.z = o.z > 0.f ? o.z : expm1f(o.z);
    o.w = o.w > 0.f ? o.w : expm1f(o.w);
    *(float4*)(hout + (size_t)n * NH + lane * 4) = o;
}

// ---------------- launch -----------------------------------------------------
extern "C" void kernel_launch(void* const* d_in, const int* in_sizes, int n_in,
                              void* d_out, int out_size) {
    const float* x    = (const float*)d_in[0];
    const int*   s    = (const int*)  d_in[1];
    const int*   t    = (const int*)  d_in[2];
    const float* fc1W = (const float*)d_in[3];
    const float* fc1b = (const float*)d_in[4];
    const float* fcsW = (const float*)d_in[5];
    const float* fcsb = (const float*)d_in[6];
    const float* a1   = (const float*)d_in[7];
    const float* a2   = (const float*)d_in[8];
    const float* fc2W = (const float*)d_in[9];
    const float* fc2b = (const float*)d_in[10];
    float* out = (float*)d_out;

    float *px, *ph, *pxn, *phn;
    int *pdeg;
    cudaGetSymbolAddress((void**)&px,  g_x);
    cudaGetSymbolAddress((void**)&ph,  g_h);
    cudaGetSymbolAddress((void**)&pxn, g_xn);
    cudaGetSymbolAddress((void**)&phn, g_hn);
    cudaGetSymbolAddress((void**)&pdeg, g_deg);

    const size_t smem128 = (size_t)(128 + 128) * 33 * sizeof(float);  // 33792 B
    const size_t smem64  = (size_t)(128 + 64)  * 33 * sizeof(float);  // 25344 B

    // CSR build (runs every replay; inputs are constant so result is stable)
    cudaMemsetAsync(pdeg, 0, NN * sizeof(int), 0);
    hist_kernel<<<(EE + 255) / 256, 256>>>(s);
    scan_kernel<<<1, 1024>>>();
    scatter_kernel<<<(EE + 255) / 256, 256>>>(s, t);

    const int gx = (NN + 127) / 128;   // 391 row-tiles

    // fc1: x = relu(x_in @ fc1W^T + fc1b)
    gemm_kernel<128, 1><<<dim3(gx, 1), 256, smem128>>>(x, x, fc1W, fc1b, px, px, NN, NIN);

    for (int i = 0; i < NHOP; i++) {
        const float* W   = fcsW + (size_t)i * NH * NH;
        const float* b   = fcsb + (size_t)i * NH;
        const float* a1i = a1   + (size_t)i * NH;
        const float* a2i = a2   + (size_t)i * NH;
        // hop 0: h == x, so hn == xn — skip the second GEMM part
        int parts = (i == 0) ? 1 : 2;
        gemm_kernel<128, 0><<<dim3(gx, parts), 256, smem128>>>(px, ph, W, b, pxn, phn, NN, NH);
        const float* hnp = (i == 0) ? pxn : phn;
        vec_kernel<<<(NN + 7) / 8, 256>>>(pxn, hnp, a1i, a2i);
        agg_kernel<<<(NN + 7) / 8, 256>>>(pxn, hnp, ph);
    }

    // out = h @ fc2W^T + fc2b
    gemm_kernel<64, 0><<<dim3(gx, 1), 256, smem64>>>(ph, ph, fc2W, fc2b, out, out, NN, NH);
    (void)in_sizes; (void)n_in; (void)out_size;
}

// round 2
// speedup vs baseline: 1.1686x; 1.1686x over previous
#include <cuda_runtime.h>
#include <math.h>

#define NN 50000
#define EE 800000
#define NIN 256
#define NH 128
#define NOUT 64
#define NHOP 10

typedef unsigned long long u64;

// ---------------- scratch (static device memory; no allocations) -------------
__device__ float g_x [(size_t)NN * NH];   // fc1 output (constant across hops)
__device__ float g_h [(size_t)NN * NH];   // current h
__device__ float g_xn[(size_t)NN * NH];   // x @ W_i + b
__device__ float g_hn[(size_t)NN * NH];   // h @ W_i + b
__device__ float g_x1[NN];
__device__ float g_h1[NN];
__device__ float g_w2[NN];
__device__ int   g_deg[NN];
__device__ int   g_rowptr[NN + 1];
__device__ int   g_cursor[NN];
__device__ int   g_et[EE];

// ---------------- packed f32x2 helpers ---------------------------------------
__device__ __forceinline__ void ffma2(u64& acc, u64 a, u64 b) {
    asm("fma.rn.f32x2 %0, %1, %2, %0;" : "+l"(acc) : "l"(a), "l"(b));
}
__device__ __forceinline__ u64 dup2(float w) {
    u64 r; asm("mov.b64 %0, {%1, %1};" : "=l"(r) : "f"(w)); return r;
}
__device__ __forceinline__ void unpack2(u64 v, float& lo, float& hi) {
    asm("mov.b64 {%0, %1}, %2;" : "=f"(lo), "=f"(hi) : "l"(v));
}

// ---------------- CSR build --------------------------------------------------
__global__ void hist_kernel(const int* __restrict__ s) {
    int e = blockIdx.x * blockDim.x + threadIdx.x;
    if (e < EE) atomicAdd(&g_deg[s[e]], 1);
}

__global__ void scan_kernel() {
    __shared__ int sh[1024];
    __shared__ int carry_s;
    int tid = threadIdx.x;
    if (tid == 0) { carry_s = 0; g_rowptr[0] = 0; }
    __syncthreads();
    for (int base = 0; base < NN; base += 1024) {
        int v = (base + tid < NN) ? g_deg[base + tid] : 0;
        sh[tid] = v;
        __syncthreads();
        for (int off = 1; off < 1024; off <<= 1) {
            int add = (tid >= off) ? sh[tid - off] : 0;
            __syncthreads();
            sh[tid] += add;
            __syncthreads();
        }
        int incl = sh[tid];
        int c = carry_s;
        if (base + tid < NN) {
            g_rowptr[base + tid + 1] = c + incl;
            g_cursor[base + tid]     = c + incl - v;
        }
        __syncthreads();
        if (tid == 0) carry_s = c + sh[1023];
        __syncthreads();
    }
}

__global__ void scatter_kernel(const int* __restrict__ s, const int* __restrict__ t) {
    int e = blockIdx.x * blockDim.x + threadIdx.x;
    if (e < EE) {
        int pos = atomicAdd(&g_cursor[s[e]], 1);
        g_et[pos] = t[e];
    }
}

// ---------------- f32x2 tiled GEMM: C = act(A @ W^T + b) ---------------------
// A: [nrows, K] row-major, W: [BN, K] row-major, C: [nrows, BN].
// Block tile 128 x BN, 256 threads, thread tile 8 rows x (BN/16) cols.
// Smem is k-major: As[KC][LDA], Ws[KC][LDW].
// Inner product uses fma.rn.f32x2 on row-pairs (packed) x col-broadcast.
// FUSE=1: epilogue also computes x1 = C.a1, w2 = exp(lrelu(C.a1 + C.a2))
//         (blockIdx.y==0) and h1 = C.a2 (blockIdx.y==1, or y==0 when hop0).
template <int BN, int ACT, int FUSE>
__global__ __launch_bounds__(256, 2)
void gemm_kernel(const float* __restrict__ A0, const float* __restrict__ A1,
                 const float* __restrict__ W,  const float* __restrict__ bias,
                 float* __restrict__ C0, float* __restrict__ C1,
                 const float* __restrict__ a1v, const float* __restrict__ a2v,
                 float* __restrict__ x1o, float* __restrict__ h1o, float* __restrict__ w2o,
                 int nrows, int K, int hop0) {
    constexpr int KC  = 32;
    constexpr int BM  = 128;
    constexpr int LDA = BM + 4;      // 132 (mult of 4: keeps 16B alignment)
    constexpr int LDW = BN + 4;
    constexpr int CQ  = BN / 64;     // col float4-quads per thread (2 or 1)
    constexpr int WIT = BN / 32;     // W loader iterations

    const float* A = blockIdx.y ? A1 : A0;
    float*       C = blockIdx.y ? C1 : C0;

    extern __shared__ float smem[];
    float* As = smem;                // [KC][LDA]
    float* Ws = smem + KC * LDA;     // [KC][LDW]

    const int tid = threadIdx.x;
    const int tm = tid >> 4;         // 0..15 -> rows tm*4..+3 and 64+tm*4..+3
    const int tj = tid & 15;         // 0..15 -> cols tj*4..+3 (and 64+tj*4..+3)
    const int rbase = blockIdx.x * BM;

    u64 acc[4][CQ * 4];              // 4 row-pairs x 8(or 4) cols
#pragma unroll
    for (int p = 0; p < 4; p++)
#pragma unroll
        for (int c = 0; c < CQ * 4; c++) acc[p][c] = 0ull;

    // ---- A prefetch registers ----
    float4 pa[4];
    {
        const int kc = 0;
#pragma unroll
        for (int it = 0; it < 4; it++) {
            int idx = tid + it * 256;
            int r = idx >> 3, kq = idx & 7;
            int row = rbase + r;
            pa[it] = (row < nrows) ? *(const float4*)(A + (size_t)row * K + kc + kq * 4)
                                   : make_float4(0.f, 0.f, 0.f, 0.f);
        }
    }

    const int nch = K / KC;
    for (int ch = 0; ch < nch; ch++) {
        if (ch > 0) __syncthreads();   // previous compute done before overwrite

        // W tile: issue LDGs first (latency overlapped by A stores)
        float4 pw[WIT];
#pragma unroll
        for (int it = 0; it < WIT; it++) {
            int idx = tid + it * 256;
            int r = idx >> 3, kq = idx & 7;
            pw[it] = *(const float4*)(W + (size_t)r * K + ch * KC + kq * 4);
        }
        // store A tile (transposed, k-major)
#pragma unroll
        for (int it = 0; it < 4; it++) {
            int idx = tid + it * 256;
            int r = idx >> 3, kq = idx & 7;
            As[(kq * 4 + 0) * LDA + r] = pa[it].x;
            As[(kq * 4 + 1) * LDA + r] = pa[it].y;
            As[(kq * 4 + 2) * LDA + r] = pa[it].z;
            As[(kq * 4 + 3) * LDA + r] = pa[it].w;
        }
        // store W tile (transposed, k-major)
#pragma unroll
        for (int it = 0; it < WIT; it++) {
            int idx = tid + it * 256;
            int r = idx >> 3, kq = idx & 7;
            Ws[(kq * 4 + 0) * LDW + r] = pw[it].x;
            Ws[(kq * 4 + 1) * LDW + r] = pw[it].y;
            Ws[(kq * 4 + 2) * LDW + r] = pw[it].z;
            Ws[(kq * 4 + 3) * LDW + r] = pw[it].w;
        }
        // prefetch next A tile
        if (ch + 1 < nch) {
            const int kc = (ch + 1) * KC;
#pragma unroll
            for (int it = 0; it < 4; it++) {
                int idx = tid + it * 256;
                int r = idx >> 3, kq = idx & 7;
                int row = rbase + r;
                pa[it] = (row < nrows) ? *(const float4*)(A + (size_t)row * K + kc + kq * 4)
                                       : make_float4(0.f, 0.f, 0.f, 0.f);
            }
        }
        __syncthreads();

        const float* Asb = As + tm * 4;
        const float* Wsb = Ws + tj * 4;
#pragma unroll
        for (int k = 0; k < KC; k++) {
            const u64* ap = (const u64*)(Asb + k * LDA);
            u64 a01 = ap[0];
            u64 a23 = ap[1];
            const u64* ap2 = (const u64*)(Asb + k * LDA + 64);
            u64 a45 = ap2[0];
            u64 a67 = ap2[1];
            float4 w0 = *(const float4*)(Wsb + k * LDW);
            u64 wd0 = dup2(w0.x), wd1 = dup2(w0.y), wd2 = dup2(w0.z), wd3 = dup2(w0.w);
            ffma2(acc[0][0], a01, wd0); ffma2(acc[1][0], a23, wd0);
            ffma2(acc[2][0], a45, wd0); ffma2(acc[3][0], a67, wd0);
            ffma2(acc[0][1], a01, wd1); ffma2(acc[1][1], a23, wd1);
            ffma2(acc[2][1], a45, wd1); ffma2(acc[3][1], a67, wd1);
            ffma2(acc[0][2], a01, wd2); ffma2(acc[1][2], a23, wd2);
            ffma2(acc[2][2], a45, wd2); ffma2(acc[3][2], a67, wd2);
            ffma2(acc[0][3], a01, wd3); ffma2(acc[1][3], a23, wd3);
            ffma2(acc[2][3], a45, wd3); ffma2(acc[3][3], a67, wd3);
            if (CQ == 2) {
                float4 w1 = *(const float4*)(Wsb + k * LDW + 64);
                u64 wd4 = dup2(w1.x), wd5 = dup2(w1.y), wd6 = dup2(w1.z), wd7 = dup2(w1.w);
                ffma2(acc[0][4], a01, wd4); ffma2(acc[1][4], a23, wd4);
                ffma2(acc[2][4], a45, wd4); ffma2(acc[3][4], a67, wd4);
                ffma2(acc[0][5], a01, wd5); ffma2(acc[1][5], a23, wd5);
                ffma2(acc[2][5], a45, wd5); ffma2(acc[3][5], a67, wd5);
                ffma2(acc[0][6], a01, wd6); ffma2(acc[1][6], a23, wd6);
                ffma2(acc[2][6], a45, wd6); ffma2(acc[3][6], a67, wd6);
                ffma2(acc[0][7], a01, wd7); ffma2(acc[1][7], a23, wd7);
                ffma2(acc[2][7], a45, wd7); ffma2(acc[3][7], a67, wd7);
            }
        }
    }

    // ---- epilogue: unpack, bias, (act), store, optional fused attn vectors --
    float bv[CQ * 4];
#pragma unroll
    for (int c = 0; c < CQ * 4; c++) {
        int col = (c < 4) ? tj * 4 + c : 64 + tj * 4 + (c - 4);
        bv[c] = bias[col];
    }
    float v[8][CQ * 4];
#pragma unroll
    for (int p = 0; p < 4; p++)
#pragma unroll
        for (int c = 0; c < CQ * 4; c++) {
            float lo, hi;
            unpack2(acc[p][c], lo, hi);
            lo += bv[c]; hi += bv[c];
            if (ACT) { lo = fmaxf(lo, 0.f); hi = fmaxf(hi, 0.f); }
            v[2 * p][c] = lo;
            v[2 * p + 1][c] = hi;
        }

#pragma unroll
    for (int i = 0; i < 8; i++) {
        int row = rbase + ((i < 4) ? tm * 4 + i : 64 + tm * 4 + (i - 4));
        if (row < nrows) {
            float4 o0 = make_float4(v[i][0], v[i][1], v[i][2], v[i][3]);
            *(float4*)(C + (size_t)row * BN + tj * 4) = o0;
            if (CQ == 2) {
                float4 o1 = make_float4(v[i][4], v[i][5], v[i][6], v[i][7]);
                *(float4*)(C + (size_t)row * BN + 64 + tj * 4) = o1;
            }
        }
    }

    if (FUSE && CQ == 2) {
        float a1c[8], a2c[8];
        bool needA1 = (blockIdx.y == 0);
#pragma unroll
        for (int c = 0; c < 8; c++) {
            int col = (c < 4) ? tj * 4 + c : 64 + tj * 4 + (c - 4);
            a1c[c] = needA1 ? a1v[col] : 0.f;
            a2c[c] = a2v[col];
        }
#pragma unroll
        for (int i = 0; i < 8; i++) {
            float s1 = 0.f, s2 = 0.f;
#pragma unroll
            for (int c = 0; c < 8; c++) {
                s1 = fmaf(v[i][c], a1c[c], s1);
                s2 = fmaf(v[i][c], a2c[c], s2);
            }
#pragma unroll
            for (int off = 8; off; off >>= 1) {
                s1 += __shfl_xor_sync(0xffffffffu, s1, off);
                s2 += __shfl_xor_sync(0xffffffffu, s2, off);
            }
            int row = rbase + ((i < 4) ? tm * 4 + i : 64 + tm * 4 + (i - 4));
            if (tj == 0 && row < nrows) {
                if (blockIdx.y == 0) {
                    x1o[row] = s1;
                    float z = s1 + s2;
                    z = z > 0.f ? z : 0.2f * z;
                    w2o[row] = __expf(z);
                    if (hop0) h1o[row] = s2;   // h == x at hop 0
                } else {
                    h1o[row] = s2;
                }
            }
        }
    }
}

// ---------------- CSR aggregation (one warp per destination node) ------------
// h_out[n] = elu( (sum_e w1_e * hn[t_e] + w2[n]*xn[n]) / (sum_e w1_e + w2[n]) )
__global__ void agg_kernel(const float* __restrict__ xn, const float* __restrict__ hn,
                           float* __restrict__ hout) {
    int n = (blockIdx.x * blockDim.x + threadIdx.x) >> 5;
    int lane = threadIdx.x & 31;
    if (n >= NN) return;

    float x1n = g_x1[n];
    float w2n = g_w2[n];
    float4 acc = *(const float4*)(xn + (size_t)n * NH + lane * 4);
    acc.x *= w2n; acc.y *= w2n; acc.z *= w2n; acc.w *= w2n;
    float div = w2n;

    int e  = g_rowptr[n];
    int e1 = g_rowptr[n + 1];
    for (; e < e1; e++) {
        int t = g_et[e];
        float z = x1n + g_h1[t];
        z = z > 0.f ? z : 0.2f * z;
        float w = __expf(z);
        div += w;
        float4 hv = *(const float4*)(hn + (size_t)t * NH + lane * 4);
        acc.x = fmaf(w, hv.x, acc.x);
        acc.y = fmaf(w, hv.y, acc.y);
        acc.z = fmaf(w, hv.z, acc.z);
        acc.w = fmaf(w, hv.w, acc.w);
    }
    float inv = 1.0f / div;
    float4 o;
    o.x = acc.x * inv; o.y = acc.y * inv; o.z = acc.z * inv; o.w = acc.w * inv;
    o.x = o.x > 0.f ? o.x : expm1f(o.x);
    o.y = o.y > 0.f ? o.y : expm1f(o.y);
    o.z = o.z > 0.f ? o.z : expm1f(o.z);
    o.w = o.w > 0.f ? o.w : expm1f(o.w);
    *(float4*)(hout + (size_t)n * NH + lane * 4) = o;
}

// ---------------- launch -----------------------------------------------------
extern "C" void kernel_launch(void* const* d_in, const int* in_sizes, int n_in,
                              void* d_out, int out_size) {
    const float* x    = (const float*)d_in[0];
    const int*   s    = (const int*)  d_in[1];
    const int*   t    = (const int*)  d_in[2];
    const float* fc1W = (const float*)d_in[3];
    const float* fc1b = (const float*)d_in[4];
    const float* fcsW = (const float*)d_in[5];
    const float* fcsb = (const float*)d_in[6];
    const float* a1   = (const float*)d_in[7];
    const float* a2   = (const float*)d_in[8];
    const float* fc2W = (const float*)d_in[9];
    const float* fc2b = (const float*)d_in[10];
    float* out = (float*)d_out;

    float *px, *ph, *pxn, *phn, *px1, *ph1, *pw2;
    int *pdeg;
    cudaGetSymbolAddress((void**)&px,  g_x);
    cudaGetSymbolAddress((void**)&ph,  g_h);
    cudaGetSymbolAddress((void**)&pxn, g_xn);
    cudaGetSymbolAddress((void**)&phn, g_hn);
    cudaGetSymbolAddress((void**)&px1, g_x1);
    cudaGetSymbolAddress((void**)&ph1, g_h1);
    cudaGetSymbolAddress((void**)&pw2, g_w2);
    cudaGetSymbolAddress((void**)&pdeg, g_deg);

    const size_t smem128 = (size_t)32 * (132 + 132) * sizeof(float);  // 33792 B
    const size_t smem64  = (size_t)32 * (132 + 68)  * sizeof(float);  // 25600 B

    // CSR build (runs every replay; inputs are constant so result is stable)
    cudaMemsetAsync(pdeg, 0, NN * sizeof(int), 0);
    hist_kernel<<<(EE + 255) / 256, 256>>>(s);
    scan_kernel<<<1, 1024>>>();
    scatter_kernel<<<(EE + 255) / 256, 256>>>(s, t);

    const int gx = (NN + 127) / 128;   // 391 row-tiles

    // fc1: x = relu(x_in @ fc1W^T + fc1b)
    gemm_kernel<128, 1, 0><<<dim3(gx, 1), 256, smem128>>>(
        x, x, fc1W, fc1b, px, px, (const float*)0, (const float*)0,
        (float*)0, (float*)0, (float*)0, NN, NIN, 0);

    for (int i = 0; i < NHOP; i++) {
        const float* W   = fcsW + (size_t)i * NH * NH;
        const float* b   = fcsb + (size_t)i * NH;
        const float* a1i = a1   + (size_t)i * NH;
        const float* a2i = a2   + (size_t)i * NH;
        // hop 0: h == x, so hn == xn — skip the second GEMM part
        int parts = (i == 0) ? 1 : 2;
        gemm_kernel<128, 0, 1><<<dim3(gx, parts), 256, smem128>>>(
            px, ph, W, b, pxn, phn, a1i, a2i, px1, ph1, pw2, NN, NH, (i == 0) ? 1 : 0);
        const float* hnp = (i == 0) ? pxn : phn;
        agg_kernel<<<(NN + 7) / 8, 256>>>(pxn, hnp, ph);
    }

    // out = h @ fc2W^T + fc2b
    gemm_kernel<64, 0, 0><<<dim3(gx, 1), 256, smem64>>>(
        ph, ph, fc2W, fc2b, out, out, (const float*)0, (const float*)0,
        (float*)0, (float*)0, (float*)0, NN, NH, 0);
    (void)in_sizes; (void)n_in; (void)out_size;
}

// round 4
// speedup vs baseline: 1.5762x; 1.3487x over previous
#include <cuda_runtime.h>
#include <cuda_bf16.h>
#include <math.h>

#define NN 50000
#define EE 800000
#define NIN 256
#define NH 128
#define NOUT 64
#define NHOP 10

typedef unsigned int u32;

// ---------------- scratch (static device memory; no allocations) -------------
__device__ float g_x [(size_t)NN * NH];
__device__ float g_h [(size_t)NN * NH];
__device__ float g_xn[(size_t)NN * NH];
__device__ float g_hn[(size_t)NN * NH];
__device__ float g_x1[NN];
__device__ float g_h1[NN];
__device__ float g_w2[NN];
__device__ int   g_deg[NN];
__device__ int   g_rowptr[NN + 1];
__device__ int   g_cursor[NN];
__device__ int   g_et[EE];
// pre-split weights (bf16 hi/lo planes)
__device__ __nv_bfloat16 g_w1h[128 * 256], g_w1l[128 * 256];
__device__ __nv_bfloat16 g_wsh[NHOP * 128 * 128], g_wsl[NHOP * 128 * 128];
__device__ __nv_bfloat16 g_w2h[64 * 128],  g_w2l[64 * 128];

// ---------------- mma helper -------------------------------------------------
__device__ __forceinline__ void mma_bf16(float* d, const u32* a, const u32* b) {
    asm volatile(
        "mma.sync.aligned.m16n8k16.row.col.f32.bf16.bf16.f32 "
        "{%0,%1,%2,%3}, {%4,%5,%6,%7}, {%8,%9}, {%0,%1,%2,%3};"
        : "+f"(d[0]), "+f"(d[1]), "+f"(d[2]), "+f"(d[3])
        : "r"(a[0]), "r"(a[1]), "r"(a[2]), "r"(a[3]), "r"(b[0]), "r"(b[1]));
}

// ---------------- weight pre-split kernel ------------------------------------
__global__ void convW_kernel(const float* __restrict__ fc1W,
                             const float* __restrict__ fcsW,
                             const float* __restrict__ fc2W) {
    int i = blockIdx.x * blockDim.x + threadIdx.x;
    float v;
    __nv_bfloat16 *H, *L;
    if (i < 32768) {
        v = fc1W[i]; H = g_w1h + i; L = g_w1l + i;
    } else if (i < 32768 + NHOP * 16384) {
        int j = i - 32768;
        v = fcsW[j]; H = g_wsh + j; L = g_wsl + j;
    } else if (i < 32768 + NHOP * 16384 + 8192) {
        int j = i - 32768 - NHOP * 16384;
        v = fc2W[j]; H = g_w2h + j; L = g_w2l + j;
    } else return;
    __nv_bfloat16 h = __float2bfloat16(v);
    *H = h;
    *L = __float2bfloat16(v - __bfloat162float(h));
}

// ---------------- CSR build --------------------------------------------------
__global__ void hist_kernel(const int* __restrict__ s) {
    int e = blockIdx.x * blockDim.x + threadIdx.x;
    if (e < EE) atomicAdd(&g_deg[s[e]], 1);
}

__global__ void scan_kernel() {
    __shared__ int sh[1024];
    __shared__ int carry_s;
    int tid = threadIdx.x;
    if (tid == 0) { carry_s = 0; g_rowptr[0] = 0; }
    __syncthreads();
    for (int base = 0; base < NN; base += 1024) {
        int v = (base + tid < NN) ? g_deg[base + tid] : 0;
        sh[tid] = v;
        __syncthreads();
        for (int off = 1; off < 1024; off <<= 1) {
            int add = (tid >= off) ? sh[tid - off] : 0;
            __syncthreads();
            sh[tid] += add;
            __syncthreads();
        }
        int incl = sh[tid];
        int c = carry_s;
        if (base + tid < NN) {
            g_rowptr[base + tid + 1] = c + incl;
            g_cursor[base + tid]     = c + incl - v;
        }
        __syncthreads();
        if (tid == 0) carry_s = c + sh[1023];
        __syncthreads();
    }
}

__global__ void scatter_kernel(const int* __restrict__ s, const int* __restrict__ t) {
    int e = blockIdx.x * blockDim.x + threadIdx.x;
    if (e < EE) {
        int pos = atomicAdd(&g_cursor[s[e]], 1);
        g_et[pos] = t[e];
    }
}

// ---------------- bf16 3-product mma GEMM ------------------------------------
// C[nrows,BN] = act(A[nrows,KTOT] @ W[BN,KTOT]^T + bias), W pre-split hi/lo.
// Block 128 x BN, 8 warps in 2x4, warp tile 64 x (BN/4), m16n8k16 fragments.
// FUSE: also x1 = C.a1, w2 = exp(lrelu(C.a1 + C.a2)) [part0], h1 = C.a2 [part1].
template <int KTOT, int BN, int ACT, int FUSE>
__global__ __launch_bounds__(256)
void mma_gemm(const float* __restrict__ A0, const float* __restrict__ A1,
              const __nv_bfloat16* __restrict__ Whg, const __nv_bfloat16* __restrict__ Wlg,
              const float* __restrict__ bias,
              float* __restrict__ C0, float* __restrict__ C1,
              const float* __restrict__ a1v, const float* __restrict__ a2v,
              float* __restrict__ x1o, float* __restrict__ h1o, float* __restrict__ w2o,
              int nrows, int hop0) {
    constexpr int NT  = BN / 32;        // n-tiles per warp (4 or 2)
    constexpr int NCH = KTOT / 32;      // K chunks of 32
    constexpr int WIT = BN / 64;        // W uint4 loader iters (2 or 1)
    constexpr int SP  = 20;             // padded row stride in u32 (conflict-free)

    __shared__ float biasS[BN];
    __shared__ float a1S[128], a2S[128];
    __shared__ float s1p[4][128], s2p[4][128];
    __shared__ u32 Ah[128 * SP], Al[128 * SP];
    __shared__ u32 Wsh[BN * SP], Wsl[BN * SP];

    const int tid = threadIdx.x;
    const int wid = tid >> 5, lane = tid & 31;
    const int wm = wid >> 2, wn = wid & 3;     // warp grid 2 x 4
    const int part = blockIdx.y;
    const float* A = part ? A1 : A0;
    float*       C = part ? C1 : C0;
    const int rbase = blockIdx.x * 128;

    if (tid < BN) biasS[tid] = bias[tid];
    if (FUSE && tid < 128) { a1S[tid] = a1v[tid]; a2S[tid] = a2v[tid]; }

    float acc[4][NT][4];
#pragma unroll
    for (int mt = 0; mt < 4; mt++)
#pragma unroll
        for (int nt = 0; nt < NT; nt++)
#pragma unroll
            for (int q = 0; q < 4; q++) acc[mt][nt][q] = 0.f;

    // ---- chunk 0 prefetch ----
    float4 pa[4];
    uint4 pwh[WIT], pwl[WIT];
#pragma unroll
    for (int it = 0; it < 4; it++) {
        int idx = tid + it * 256;
        int r = idx >> 3, kq = idx & 7;
        int row = rbase + r;
        pa[it] = (row < nrows) ? *(const float4*)(A + (size_t)row * KTOT + kq * 4)
                               : make_float4(0.f, 0.f, 0.f, 0.f);
    }
#pragma unroll
    for (int it = 0; it < WIT; it++) {
        int idx = tid + it * 256;
        int r = idx >> 2, q = idx & 3;
        pwh[it] = ((const uint4*)(Whg + (size_t)r * KTOT))[q];
        pwl[it] = ((const uint4*)(Wlg + (size_t)r * KTOT))[q];
    }

    for (int c = 0; c < NCH; c++) {
        // ---- STS A (split fp32 -> bf16 hi/lo) ----
#pragma unroll
        for (int it = 0; it < 4; it++) {
            int idx = tid + it * 256;
            int r = idx >> 3, kq = idx & 7;
            float4 v = pa[it];
            __nv_bfloat162 hxy = __floats2bfloat162_rn(v.x, v.y);
            __nv_bfloat162 hzw = __floats2bfloat162_rn(v.z, v.w);
            float2 fxy = __bfloat1622float2(hxy);
            float2 fzw = __bfloat1622float2(hzw);
            __nv_bfloat162 lxy = __floats2bfloat162_rn(v.x - fxy.x, v.y - fxy.y);
            __nv_bfloat162 lzw = __floats2bfloat162_rn(v.z - fzw.x, v.w - fzw.y);
            int o = r * SP + kq * 2;
            Ah[o]     = *(u32*)&hxy;  Ah[o + 1] = *(u32*)&hzw;
            Al[o]     = *(u32*)&lxy;  Al[o + 1] = *(u32*)&lzw;
        }
        // ---- STS W (already bf16) ----
#pragma unroll
        for (int it = 0; it < WIT; it++) {
            int idx = tid + it * 256;
            int r = idx >> 2, q = idx & 3;
            *(uint4*)&Wsh[r * SP + q * 4] = pwh[it];
            *(uint4*)&Wsl[r * SP + q * 4] = pwl[it];
        }
        __syncthreads();

        // ---- prefetch next chunk ----
        if (c + 1 < NCH) {
            const int kc = (c + 1) * 32;
#pragma unroll
            for (int it = 0; it < 4; it++) {
                int idx = tid + it * 256;
                int r = idx >> 3, kq = idx & 7;
                int row = rbase + r;
                pa[it] = (row < nrows) ? *(const float4*)(A + (size_t)row * KTOT + kc + kq * 4)
                                       : make_float4(0.f, 0.f, 0.f, 0.f);
            }
#pragma unroll
            for (int it = 0; it < WIT; it++) {
                int idx = tid + it * 256;
                int r = idx >> 2, q = idx & 3;
                pwh[it] = ((const uint4*)(Whg + (size_t)r * KTOT + kc))[q];
                pwl[it] = ((const uint4*)(Wlg + (size_t)r * KTOT + kc))[q];
            }
        }

        // ---- compute: 2 x k16 steps ----
#pragma unroll
        for (int s = 0; s < 2; s++) {
            u32 ah[4][4], al[4][4], bh[NT][2], bl[NT][2];
            const int abase = (wm * 64 + (lane >> 2)) * SP + (lane & 3) + s * 8;
#pragma unroll
            for (int mt = 0; mt < 4; mt++) {
                int o = abase + mt * 16 * SP;
                ah[mt][0] = Ah[o];               ah[mt][1] = Ah[o + 8 * SP];
                ah[mt][2] = Ah[o + 4];           ah[mt][3] = Ah[o + 8 * SP + 4];
                al[mt][0] = Al[o];               al[mt][1] = Al[o + 8 * SP];
                al[mt][2] = Al[o + 4];           al[mt][3] = Al[o + 8 * SP + 4];
            }
            const int bbase = (wn * NT * 8 + (lane >> 2)) * SP + (lane & 3) + s * 8;
#pragma unroll
            for (int nt = 0; nt < NT; nt++) {
                int o = bbase + nt * 8 * SP;
                bh[nt][0] = Wsh[o];  bh[nt][1] = Wsh[o + 4];
                bl[nt][0] = Wsl[o];  bl[nt][1] = Wsl[o + 4];
            }
#pragma unroll
            for (int mt = 0; mt < 4; mt++)
#pragma unroll
                for (int nt = 0; nt < NT; nt++) {
                    mma_bf16(acc[mt][nt], ah[mt], bh[nt]);
                    mma_bf16(acc[mt][nt], ah[mt], bl[nt]);
                    mma_bf16(acc[mt][nt], al[mt], bh[nt]);
                }
        }
        if (c + 1 < NCH) __syncthreads();
    }

    // ---- epilogue: bias/act, C store, fused attention-vector partials ----
#pragma unroll
    for (int mt = 0; mt < 4; mt++) {
        int lr0 = wm * 64 + mt * 16 + (lane >> 2);
        float s1a = 0.f, s2a = 0.f, s1b = 0.f, s2b = 0.f;
#pragma unroll
        for (int nt = 0; nt < NT; nt++) {
            int col = wn * NT * 8 + nt * 8 + (lane & 3) * 2;
            float d0 = acc[mt][nt][0] + biasS[col];
            float d1 = acc[mt][nt][1] + biasS[col + 1];
            float d2 = acc[mt][nt][2] + biasS[col];
            float d3 = acc[mt][nt][3] + biasS[col + 1];
            if (ACT) {
                d0 = fmaxf(d0, 0.f); d1 = fmaxf(d1, 0.f);
                d2 = fmaxf(d2, 0.f); d3 = fmaxf(d3, 0.f);
            }
            if (FUSE) {
                s1a = fmaf(d0, a1S[col], fmaf(d1, a1S[col + 1], s1a));
                s2a = fmaf(d0, a2S[col], fmaf(d1, a2S[col + 1], s2a));
                s1b = fmaf(d2, a1S[col], fmaf(d3, a1S[col + 1], s1b));
                s2b = fmaf(d2, a2S[col], fmaf(d3, a2S[col + 1], s2b));
            }
            int row0 = rbase + lr0;
            int row1 = row0 + 8;
            if (row0 < nrows) *(float2*)(C + (size_t)row0 * BN + col) = make_float2(d0, d1);
            if (row1 < nrows) *(float2*)(C + (size_t)row1 * BN + col) = make_float2(d2, d3);
        }
        if (FUSE) {
#pragma unroll
            for (int off = 1; off <= 2; off <<= 1) {
                s1a += __shfl_xor_sync(0xffffffffu, s1a, off);
                s2a += __shfl_xor_sync(0xffffffffu, s2a, off);
                s1b += __shfl_xor_sync(0xffffffffu, s1b, off);
                s2b += __shfl_xor_sync(0xffffffffu, s2b, off);
            }
            if ((lane & 3) == 0) {
                s1p[wn][lr0]     = s1a;  s2p[wn][lr0]     = s2a;
                s1p[wn][lr0 + 8] = s1b;  s2p[wn][lr0 + 8] = s2b;
            }
        }
    }

    if (FUSE) {
        __syncthreads();
        if (tid < 128) {
            int row = rbase + tid;
            if (row < nrows) {
                float s1 = s1p[0][tid] + s1p[1][tid] + s1p[2][tid] + s1p[3][tid];
                float s2 = s2p[0][tid] + s2p[1][tid] + s2p[2][tid] + s2p[3][tid];
                if (part == 0) {
                    x1o[row] = s1;
                    float z = s1 + s2;
                    z = z > 0.f ? z : 0.2f * z;
                    w2o[row] = __expf(z);
                    if (hop0) h1o[row] = s2;
                } else {
                    h1o[row] = s2;
                }
            }
        }
    }
}

// ---------------- CSR aggregation (one warp per destination node) ------------
__global__ void agg_kernel(const float* __restrict__ xn, const float* __restrict__ hn,
                           float* __restrict__ hout) {
    int n = (blockIdx.x * blockDim.x + threadIdx.x) >> 5;
    int lane = threadIdx.x & 31;
    if (n >= NN) return;

    float x1n = g_x1[n];
    float w2n = g_w2[n];
    float4 acc = *(const float4*)(xn + (size_t)n * NH + lane * 4);
    acc.x *= w2n; acc.y *= w2n; acc.z *= w2n; acc.w *= w2n;
    float div = w2n;

    int e  = g_rowptr[n];
    int e1 = g_rowptr[n + 1];
    for (; e < e1; e++) {
        int t = g_et[e];
        float z = x1n + g_h1[t];
        z = z > 0.f ? z : 0.2f * z;
        float w = __expf(z);
        div += w;
        float4 hv = *(const float4*)(hn + (size_t)t * NH + lane * 4);
        acc.x = fmaf(w, hv.x, acc.x);
        acc.y = fmaf(w, hv.y, acc.y);
        acc.z = fmaf(w, hv.z, acc.z);
        acc.w = fmaf(w, hv.w, acc.w);
    }
    float inv = 1.0f / div;
    float4 o;
    o.x = acc.x * inv; o.y = acc.y * inv; o.z = acc.z * inv; o.w = acc.w * inv;
    o.x = o.x > 0.f ? o.x : expm1f(o.x);
    o.y = o.y > 0.f ? o.y : expm1f(o.y);
    o.z = o.z > 0.f ? o.z : expm1f(o.z);
    o.w = o.w > 0.f ? o.w : expm1f(o.w);
    *(float4*)(hout + (size_t)n * NH + lane * 4) = o;
}

// ---------------- launch -----------------------------------------------------
extern "C" void kernel_launch(void* const* d_in, const int* in_sizes, int n_in,
                              void* d_out, int out_size) {
    const float* x    = (const float*)d_in[0];
    const int*   s    = (const int*)  d_in[1];
    const int*   t    = (const int*)  d_in[2];
    const float* fc1W = (const float*)d_in[3];
    const float* fc1b = (const float*)d_in[4];
    const float* fcsW = (const float*)d_in[5];
    const float* fcsb = (const float*)d_in[6];
    const float* a1   = (const float*)d_in[7];
    const float* a2   = (const float*)d_in[8];
    const float* fc2W = (const float*)d_in[9];
    const float* fc2b = (const float*)d_in[10];
    float* out = (float*)d_out;

    float *px, *ph, *pxn, *phn, *px1, *ph1, *pw2;
    int *pdeg;
    __nv_bfloat16 *w1h, *w1l, *wsh, *wsl, *w2h, *w2l;
    cudaGetSymbolAddress((void**)&px,  g_x);
    cudaGetSymbolAddress((void**)&ph,  g_h);
    cudaGetSymbolAddress((void**)&pxn, g_xn);
    cudaGetSymbolAddress((void**)&phn, g_hn);
    cudaGetSymbolAddress((void**)&px1, g_x1);
    cudaGetSymbolAddress((void**)&ph1, g_h1);
    cudaGetSymbolAddress((void**)&pw2, g_w2);
    cudaGetSymbolAddress((void**)&pdeg, g_deg);
    cudaGetSymbolAddress((void**)&w1h, g_w1h);
    cudaGetSymbolAddress((void**)&w1l, g_w1l);
    cudaGetSymbolAddress((void**)&wsh, g_wsh);
    cudaGetSymbolAddress((void**)&wsl, g_wsl);
    cudaGetSymbolAddress((void**)&w2h, g_w2h);
    cudaGetSymbolAddress((void**)&w2l, g_w2l);

    // weight pre-split + CSR build (constant inputs -> stable every replay)
    convW_kernel<<<(32768 + NHOP * 16384 + 8192 + 255) / 256, 256>>>(fc1W, fcsW, fc2W);
    cudaMemsetAsync(pdeg, 0, NN * sizeof(int), 0);
    hist_kernel<<<(EE + 255) / 256, 256>>>(s);
    scan_kernel<<<1, 1024>>>();
    scatter_kernel<<<(EE + 255) / 256, 256>>>(s, t);

    const int gx = (NN + 127) / 128;   // 391 row-tiles

    // fc1: x = relu(x_in @ fc1W^T + fc1b)
    mma_gemm<256, 128, 1, 0><<<dim3(gx, 1), 256>>>(
        x, x, w1h, w1l, fc1b, px, px,
        (const float*)0, (const float*)0, (float*)0, (float*)0, (float*)0, NN, 0);

    for (int i = 0; i < NHOP; i++) {
        const __nv_bfloat16* Wh = wsh + (size_t)i * NH * NH;
        const __nv_bfloat16* Wl = wsl + (size_t)i * NH * NH;
        const float* b   = fcsb + (size_t)i * NH;
        const float* a1i = a1   + (size_t)i * NH;
        const float* a2i = a2   + (size_t)i * NH;
        int parts = (i == 0) ? 1 : 2;   // hop 0: h == x, skip h-path
        mma_gemm<128, 128, 0, 1><<<dim3(gx, parts), 256>>>(
            px, ph, Wh, Wl, b, pxn, phn, a1i, a2i, px1, ph1, pw2, NN, (i == 0) ? 1 : 0);
        const float* hnp = (i == 0) ? pxn : phn;
        agg_kernel<<<(NN + 7) / 8, 256>>>(pxn, hnp, ph);
    }

    // out = h @ fc2W^T + fc2b
    mma_gemm<128, 64, 0, 0><<<dim3(gx, 1), 256>>>(
        ph, ph, w2h, w2l, fc2b, out, out,
        (const float*)0, (const float*)0, (float*)0, (float*)0, (float*)0, NN, 0);
    (void)in_sizes; (void)n_in; (void)out_size;
}

// round 5
// speedup vs baseline: 1.6166x; 1.0256x over previous
#include <cuda_runtime.h>
#include <cuda_bf16.h>
#include <math.h>

#define NN 50000
#define EE 800000
#define NIN 256
#define NH 128
#define NOUT 64
#define NHOP 10

typedef unsigned int u32;

// ---------------- scratch (static device memory; no allocations) -------------
__device__ float g_x [(size_t)NN * NH];
__device__ float g_h [(size_t)NN * NH];
__device__ float g_hn[(size_t)NN * NH];
__device__ float g_xnall[(size_t)NHOP * NN * NH];   // all hops' x-path outputs
__device__ float g_x1all[NHOP * NN];
__device__ float g_w2all[NHOP * NN];
__device__ float g_h1[NN];
__device__ int   g_deg[NN];
__device__ int   g_rowptr[NN + 1];
__device__ int   g_cursor[NN];
__device__ int   g_et[EE];
// pre-split weights (bf16 hi/lo planes)
__device__ __nv_bfloat16 g_w1h[128 * 256], g_w1l[128 * 256];
__device__ __nv_bfloat16 g_wsh[NHOP * 128 * 128], g_wsl[NHOP * 128 * 128];
__device__ __nv_bfloat16 g_w2h[64 * 128],  g_w2l[64 * 128];

// ---------------- mma helper -------------------------------------------------
__device__ __forceinline__ void mma_bf16(float* d, const u32* a, const u32* b) {
    asm volatile(
        "mma.sync.aligned.m16n8k16.row.col.f32.bf16.bf16.f32 "
        "{%0,%1,%2,%3}, {%4,%5,%6,%7}, {%8,%9}, {%0,%1,%2,%3};"
        : "+f"(d[0]), "+f"(d[1]), "+f"(d[2]), "+f"(d[3])
        : "r"(a[0]), "r"(a[1]), "r"(a[2]), "r"(a[3]), "r"(b[0]), "r"(b[1]));
}

// ---------------- weight pre-split kernel ------------------------------------
__global__ void convW_kernel(const float* __restrict__ fc1W,
                             const float* __restrict__ fcsW,
                             const float* __restrict__ fc2W) {
    int i = blockIdx.x * blockDim.x + threadIdx.x;
    float v;
    __nv_bfloat16 *H, *L;
    if (i < 32768) {
        v = fc1W[i]; H = g_w1h + i; L = g_w1l + i;
    } else if (i < 32768 + NHOP * 16384) {
        int j = i - 32768;
        v = fcsW[j]; H = g_wsh + j; L = g_wsl + j;
    } else if (i < 32768 + NHOP * 16384 + 8192) {
        int j = i - 32768 - NHOP * 16384;
        v = fc2W[j]; H = g_w2h + j; L = g_w2l + j;
    } else return;
    __nv_bfloat16 h = __float2bfloat16(v);
    *H = h;
    *L = __float2bfloat16(v - __bfloat162float(h));
}

// ---------------- CSR build --------------------------------------------------
__global__ void hist_kernel(const int* __restrict__ s) {
    int e = blockIdx.x * blockDim.x + threadIdx.x;
    if (e < EE) atomicAdd(&g_deg[s[e]], 1);
}

__global__ void scan_kernel() {
    __shared__ int sh[1024];
    __shared__ int carry_s;
    int tid = threadIdx.x;
    if (tid == 0) { carry_s = 0; g_rowptr[0] = 0; }
    __syncthreads();
    for (int base = 0; base < NN; base += 1024) {
        int v = (base + tid < NN) ? g_deg[base + tid] : 0;
        sh[tid] = v;
        __syncthreads();
        for (int off = 1; off < 1024; off <<= 1) {
            int add = (tid >= off) ? sh[tid - off] : 0;
            __syncthreads();
            sh[tid] += add;
            __syncthreads();
        }
        int incl = sh[tid];
        int c = carry_s;
        if (base + tid < NN) {
            g_rowptr[base + tid + 1] = c + incl;
            g_cursor[base + tid]     = c + incl - v;
        }
        __syncthreads();
        if (tid == 0) carry_s = c + sh[1023];
        __syncthreads();
    }
}

__global__ void scatter_kernel(const int* __restrict__ s, const int* __restrict__ t) {
    int e = blockIdx.x * blockDim.x + threadIdx.x;
    if (e < EE) {
        int pos = atomicAdd(&g_cursor[s[e]], 1);
        g_et[pos] = t[e];
    }
}

// ---------------- bf16 3-product mma GEMM ------------------------------------
// C[nrows,BN] = act(A[nrows,KTOT] @ W[BN,KTOT]^T + bias), W pre-split hi/lo.
// Block 128 x BN, 8 warps in 2x4, warp tile 64 x (BN/4), m16n8k16 fragments.
// MODE 0: plain. MODE 1: h-path (also h1 = C.a2). MODE 2: batched x-path
//   (blockIdx.z = hop; also x1 = C.a1, w2 = exp(lrelu(C.a1 + C.a2)),
//    and h1 = C.a2 when hop == 0, since h == x at hop 0).
template <int KTOT, int BN, int ACT, int MODE>
__global__ __launch_bounds__(256)
void mma_gemm(const float* __restrict__ Ag,
              const __nv_bfloat16* __restrict__ Whg, const __nv_bfloat16* __restrict__ Wlg,
              const float* __restrict__ biasg,
              float* __restrict__ Cg,
              const float* __restrict__ a1g, const float* __restrict__ a2g,
              float* __restrict__ x1o, float* __restrict__ h1o, float* __restrict__ w2o,
              int nrows) {
    constexpr int NT  = BN / 32;        // n-tiles per warp (4 or 2)
    constexpr int NCH = KTOT / 32;      // K chunks of 32
    constexpr int WIT = BN / 64;        // W uint4 loader iters (2 or 1)
    constexpr int SP  = 20;             // padded row stride in u32 (conflict-free)

    __shared__ float biasS[BN];
    __shared__ float a1S[128], a2S[128];
    __shared__ float s1p[4][128], s2p[4][128];
    __shared__ u32 Ah[128 * SP], Al[128 * SP];
    __shared__ u32 Wsh[BN * SP], Wsl[BN * SP];

    const int tid = threadIdx.x;
    const int wid = tid >> 5, lane = tid & 31;
    const int wm = wid >> 2, wn = wid & 3;     // warp grid 2 x 4
    const int hop = (MODE == 2) ? blockIdx.z : 0;
    const int rbase = blockIdx.x * 128;

    const float* A = Ag;                           // MODE 2: same A (g_x) for all z
    const __nv_bfloat16* Wh = Whg + (size_t)hop * BN * KTOT;
    const __nv_bfloat16* Wl = Wlg + (size_t)hop * BN * KTOT;
    const float* bias = biasg + (size_t)hop * BN;
    float* C = Cg + (size_t)hop * NN * BN;

    if (tid < BN) biasS[tid] = bias[tid];
    if (MODE && tid < 128) {
        a1S[tid] = (MODE == 2) ? a1g[hop * 128 + tid] : 0.f;
        a2S[tid] = a2g[hop * 128 + tid];
    }

    float acc[4][NT][4];
#pragma unroll
    for (int mt = 0; mt < 4; mt++)
#pragma unroll
        for (int nt = 0; nt < NT; nt++)
#pragma unroll
            for (int q = 0; q < 4; q++) acc[mt][nt][q] = 0.f;

    // ---- chunk 0 prefetch ----
    float4 pa[4];
    uint4 pwh[WIT], pwl[WIT];
#pragma unroll
    for (int it = 0; it < 4; it++) {
        int idx = tid + it * 256;
        int r = idx >> 3, kq = idx & 7;
        int row = rbase + r;
        pa[it] = (row < nrows) ? *(const float4*)(A + (size_t)row * KTOT + kq * 4)
                               : make_float4(0.f, 0.f, 0.f, 0.f);
    }
#pragma unroll
    for (int it = 0; it < WIT; it++) {
        int idx = tid + it * 256;
        int r = idx >> 2, q = idx & 3;
        pwh[it] = ((const uint4*)(Wh + (size_t)r * KTOT))[q];
        pwl[it] = ((const uint4*)(Wl + (size_t)r * KTOT))[q];
    }

    for (int c = 0; c < NCH; c++) {
        // ---- STS A (split fp32 -> bf16 hi/lo) ----
#pragma unroll
        for (int it = 0; it < 4; it++) {
            int idx = tid + it * 256;
            int r = idx >> 3, kq = idx & 7;
            float4 v = pa[it];
            __nv_bfloat162 hxy = __floats2bfloat162_rn(v.x, v.y);
            __nv_bfloat162 hzw = __floats2bfloat162_rn(v.z, v.w);
            float2 fxy = __bfloat1622float2(hxy);
            float2 fzw = __bfloat1622float2(hzw);
            __nv_bfloat162 lxy = __floats2bfloat162_rn(v.x - fxy.x, v.y - fxy.y);
            __nv_bfloat162 lzw = __floats2bfloat162_rn(v.z - fzw.x, v.w - fzw.y);
            int o = r * SP + kq * 2;
            Ah[o]     = *(u32*)&hxy;  Ah[o + 1] = *(u32*)&hzw;
            Al[o]     = *(u32*)&lxy;  Al[o + 1] = *(u32*)&lzw;
        }
        // ---- STS W (already bf16) ----
#pragma unroll
        for (int it = 0; it < WIT; it++) {
            int idx = tid + it * 256;
            int r = idx >> 2, q = idx & 3;
            *(uint4*)&Wsh[r * SP + q * 4] = pwh[it];
            *(uint4*)&Wsl[r * SP + q * 4] = pwl[it];
        }
        __syncthreads();

        // ---- prefetch next chunk ----
        if (c + 1 < NCH) {
            const int kc = (c + 1) * 32;
#pragma unroll
            for (int it = 0; it < 4; it++) {
                int idx = tid + it * 256;
                int r = idx >> 3, kq = idx & 7;
                int row = rbase + r;
                pa[it] = (row < nrows) ? *(const float4*)(A + (size_t)row * KTOT + kc + kq * 4)
                                       : make_float4(0.f, 0.f, 0.f, 0.f);
            }
#pragma unroll
            for (int it = 0; it < WIT; it++) {
                int idx = tid + it * 256;
                int r = idx >> 2, q = idx & 3;
                pwh[it] = ((const uint4*)(Wh + (size_t)r * KTOT + kc))[q];
                pwl[it] = ((const uint4*)(Wl + (size_t)r * KTOT + kc))[q];
            }
        }

        // ---- compute: 2 x k16 steps ----
#pragma unroll
        for (int s = 0; s < 2; s++) {
            u32 ah[4][4], al[4][4], bh[NT][2], bl[NT][2];
            const int abase = (wm * 64 + (lane >> 2)) * SP + (lane & 3) + s * 8;
#pragma unroll
            for (int mt = 0; mt < 4; mt++) {
                int o = abase + mt * 16 * SP;
                ah[mt][0] = Ah[o];               ah[mt][1] = Ah[o + 8 * SP];
                ah[mt][2] = Ah[o + 4];           ah[mt][3] = Ah[o + 8 * SP + 4];
                al[mt][0] = Al[o];               al[mt][1] = Al[o + 8 * SP];
                al[mt][2] = Al[o + 4];           al[mt][3] = Al[o + 8 * SP + 4];
            }
            const int bbase = (wn * NT * 8 + (lane >> 2)) * SP + (lane & 3) + s * 8;
#pragma unroll
            for (int nt = 0; nt < NT; nt++) {
                int o = bbase + nt * 8 * SP;
                bh[nt][0] = Wsh[o];  bh[nt][1] = Wsh[o + 4];
                bl[nt][0] = Wsl[o];  bl[nt][1] = Wsl[o + 4];
            }
#pragma unroll
            for (int mt = 0; mt < 4; mt++)
#pragma unroll
                for (int nt = 0; nt < NT; nt++) {
                    mma_bf16(acc[mt][nt], ah[mt], bh[nt]);
                    mma_bf16(acc[mt][nt], ah[mt], bl[nt]);
                    mma_bf16(acc[mt][nt], al[mt], bh[nt]);
                }
        }
        if (c + 1 < NCH) __syncthreads();
    }

    // ---- epilogue: bias/act, C store, fused attention-vector partials ----
#pragma unroll
    for (int mt = 0; mt < 4; mt++) {
        int lr0 = wm * 64 + mt * 16 + (lane >> 2);
        float s1a = 0.f, s2a = 0.f, s1b = 0.f, s2b = 0.f;
#pragma unroll
        for (int nt = 0; nt < NT; nt++) {
            int col = wn * NT * 8 + nt * 8 + (lane & 3) * 2;
            float d0 = acc[mt][nt][0] + biasS[col];
            float d1 = acc[mt][nt][1] + biasS[col + 1];
            float d2 = acc[mt][nt][2] + biasS[col];
            float d3 = acc[mt][nt][3] + biasS[col + 1];
            if (ACT) {
                d0 = fmaxf(d0, 0.f); d1 = fmaxf(d1, 0.f);
                d2 = fmaxf(d2, 0.f); d3 = fmaxf(d3, 0.f);
            }
            if (MODE == 2) {
                s1a = fmaf(d0, a1S[col], fmaf(d1, a1S[col + 1], s1a));
                s1b = fmaf(d2, a1S[col], fmaf(d3, a1S[col + 1], s1b));
            }
            if (MODE) {
                s2a = fmaf(d0, a2S[col], fmaf(d1, a2S[col + 1], s2a));
                s2b = fmaf(d2, a2S[col], fmaf(d3, a2S[col + 1], s2b));
            }
            int row0 = rbase + lr0;
            int row1 = row0 + 8;
            if (row0 < nrows) *(float2*)(C + (size_t)row0 * BN + col) = make_float2(d0, d1);
            if (row1 < nrows) *(float2*)(C + (size_t)row1 * BN + col) = make_float2(d2, d3);
        }
        if (MODE) {
#pragma unroll
            for (int off = 1; off <= 2; off <<= 1) {
                s1a += __shfl_xor_sync(0xffffffffu, s1a, off);
                s2a += __shfl_xor_sync(0xffffffffu, s2a, off);
                s1b += __shfl_xor_sync(0xffffffffu, s1b, off);
                s2b += __shfl_xor_sync(0xffffffffu, s2b, off);
            }
            if ((lane & 3) == 0) {
                s1p[wn][lr0]     = s1a;  s2p[wn][lr0]     = s2a;
                s1p[wn][lr0 + 8] = s1b;  s2p[wn][lr0 + 8] = s2b;
            }
        }
    }

    if (MODE) {
        __syncthreads();
        if (tid < 128) {
            int row = rbase + tid;
            if (row < nrows) {
                float s1 = s1p[0][tid] + s1p[1][tid] + s1p[2][tid] + s1p[3][tid];
                float s2 = s2p[0][tid] + s2p[1][tid] + s2p[2][tid] + s2p[3][tid];
                if (MODE == 2) {
                    x1o[hop * NN + row] = s1;
                    float z = s1 + s2;
                    z = z > 0.f ? z : 0.2f * z;
                    w2o[hop * NN + row] = __expf(z);
                    if (hop == 0) h1o[row] = s2;
                } else {
                    h1o[row] = s2;
                }
            }
        }
    }
}

// ---------------- CSR aggregation (one warp per destination node) ------------
// Lane-parallel edge weights (32 edges at a time), shuffle-broadcast gather.
__global__ void agg_kernel(const float* __restrict__ xn, const float* __restrict__ hn,
                           const float* __restrict__ x1a, const float* __restrict__ w2a,
                           float* __restrict__ hout) {
    int n = (blockIdx.x * blockDim.x + threadIdx.x) >> 5;
    int lane = threadIdx.x & 31;
    if (n >= NN) return;

    float x1n = x1a[n];
    float w2n = w2a[n];
    float4 acc = *(const float4*)(xn + (size_t)n * NH + lane * 4);
    acc.x *= w2n; acc.y *= w2n; acc.z *= w2n; acc.w *= w2n;
    float divacc = 0.f;

    const int e0 = g_rowptr[n];
    const int e1 = g_rowptr[n + 1];
    for (int eb = e0; eb < e1; eb += 32) {
        int e = eb + lane;
        float w = 0.f;
        int tj = 0;
        if (e < e1) {
            tj = g_et[e];
            float z = x1n + __ldg(&g_h1[tj]);
            z = z > 0.f ? z : 0.2f * z;
            w = __expf(z);
        }
        divacc += w;
        int cnt = min(32, e1 - eb);
#pragma unroll 4
        for (int j = 0; j < cnt; j++) {
            float wj = __shfl_sync(0xffffffffu, w, j);
            int tjj  = __shfl_sync(0xffffffffu, tj, j);
            float4 hv = *(const float4*)(hn + (size_t)tjj * NH + lane * 4);
            acc.x = fmaf(wj, hv.x, acc.x);
            acc.y = fmaf(wj, hv.y, acc.y);
            acc.z = fmaf(wj, hv.z, acc.z);
            acc.w = fmaf(wj, hv.w, acc.w);
        }
    }
#pragma unroll
    for (int off = 16; off; off >>= 1)
        divacc += __shfl_xor_sync(0xffffffffu, divacc, off);
    float inv = 1.0f / (w2n + divacc);
    float4 o;
    o.x = acc.x * inv; o.y = acc.y * inv; o.z = acc.z * inv; o.w = acc.w * inv;
    o.x = o.x > 0.f ? o.x : expm1f(o.x);
    o.y = o.y > 0.f ? o.y : expm1f(o.y);
    o.z = o.z > 0.f ? o.z : expm1f(o.z);
    o.w = o.w > 0.f ? o.w : expm1f(o.w);
    *(float4*)(hout + (size_t)n * NH + lane * 4) = o;
}

// ---------------- launch -----------------------------------------------------
extern "C" void kernel_launch(void* const* d_in, const int* in_sizes, int n_in,
                              void* d_out, int out_size) {
    const float* x    = (const float*)d_in[0];
    const int*   s    = (const int*)  d_in[1];
    const int*   t    = (const int*)  d_in[2];
    const float* fc1W = (const float*)d_in[3];
    const float* fc1b = (const float*)d_in[4];
    const float* fcsW = (const float*)d_in[5];
    const float* fcsb = (const float*)d_in[6];
    const float* a1   = (const float*)d_in[7];
    const float* a2   = (const float*)d_in[8];
    const float* fc2W = (const float*)d_in[9];
    const float* fc2b = (const float*)d_in[10];
    float* out = (float*)d_out;

    float *px, *ph, *phn, *pxnall, *px1all, *pw2all, *ph1;
    int *pdeg;
    __nv_bfloat16 *w1h, *w1l, *wsh, *wsl, *w2h, *w2l;
    cudaGetSymbolAddress((void**)&px,  g_x);
    cudaGetSymbolAddress((void**)&ph,  g_h);
    cudaGetSymbolAddress((void**)&phn, g_hn);
    cudaGetSymbolAddress((void**)&pxnall, g_xnall);
    cudaGetSymbolAddress((void**)&px1all, g_x1all);
    cudaGetSymbolAddress((void**)&pw2all, g_w2all);
    cudaGetSymbolAddress((void**)&ph1, g_h1);
    cudaGetSymbolAddress((void**)&pdeg, g_deg);
    cudaGetSymbolAddress((void**)&w1h, g_w1h);
    cudaGetSymbolAddress((void**)&w1l, g_w1l);
    cudaGetSymbolAddress((void**)&wsh, g_wsh);
    cudaGetSymbolAddress((void**)&wsl, g_wsl);
    cudaGetSymbolAddress((void**)&w2h, g_w2h);
    cudaGetSymbolAddress((void**)&w2l, g_w2l);

    // weight pre-split + CSR build (constant inputs -> stable every replay)
    convW_kernel<<<(32768 + NHOP * 16384 + 8192 + 255) / 256, 256>>>(fc1W, fcsW, fc2W);
    cudaMemsetAsync(pdeg, 0, NN * sizeof(int), 0);
    hist_kernel<<<(EE + 255) / 256, 256>>>(s);
    scan_kernel<<<1, 1024>>>();
    scatter_kernel<<<(EE + 255) / 256, 256>>>(s, t);

    const int gx = (NN + 127) / 128;   // 391 row-tiles

    // fc1: x = relu(x_in @ fc1W^T + fc1b)
    mma_gemm<256, 128, 1, 0><<<dim3(gx, 1, 1), 256>>>(
        x, w1h, w1l, fc1b, px,
        (const float*)0, (const float*)0, (float*)0, (float*)0, (float*)0, NN);

    // batched x-path: xn_i, x1_i, w2_i for all hops (+ h1 for hop 0)
    mma_gemm<128, 128, 0, 2><<<dim3(gx, 1, NHOP), 256>>>(
        px, wsh, wsl, fcsb, pxnall, a1, a2, px1all, ph1, pw2all, NN);

    for (int i = 0; i < NHOP; i++) {
        const float* xni = pxnall + (size_t)i * NN * NH;
        if (i > 0) {
            // h-path: hn = h @ W_i^T + b_i, h1 = hn . a2_i
            mma_gemm<128, 128, 0, 1><<<dim3(gx, 1, 1), 256>>>(
                ph, wsh + (size_t)i * NH * NH, wsl + (size_t)i * NH * NH,
                fcsb + (size_t)i * NH, phn,
                (const float*)0, a2 + (size_t)i * NH, (float*)0, ph1, (float*)0, NN);
        }
        const float* hnp = (i == 0) ? xni : phn;
        agg_kernel<<<(NN + 7) / 8, 256>>>(xni, hnp, px1all + (size_t)i * NN,
                                          pw2all + (size_t)i * NN, ph);
    }

    // out = h @ fc2W^T + fc2b
    mma_gemm<128, 64, 0, 0><<<dim3(gx, 1, 1), 256>>>(
        ph, w2h, w2l, fc2b, out,
        (const float*)0, (const float*)0, (float*)0, (float*)0, (float*)0, NN);
    (void)in_sizes; (void)n_in; (void)out_size;
}